// round 9
// baseline (speedup 1.0000x reference)
#include <cuda_runtime.h>
#include <cuda_fp16.h>
#include <cstdint>

// ---------------------------------------------------------------------------
// BasisConvLayer (mode='conv', linear hat basis 4x4, F_in=F_out=16)
//
// FP16 table  T[node][u:4][v:4][fout:16]  (512 B/node, 51 MB).
//   Kernel 1 (build): ONE warp per 8-node batch covers BOTH k-halves
//     (W for 2 cells in regs); coalesced 512B x-load + prefetch; shfl
//     distribute; fma.rn.f32x2; coalesced stores.
//   Kernel 2 (edge): 8 lanes/edge, lane <-> (fout-half, us, vs): one LDG.128
//     per lane = sector-exact gather (4 sectors/edge, half of before);
//     shfl_xor(4) + split shfl_xor(2) reduce; 4 lanes red.global.add.v4.
// ---------------------------------------------------------------------------

#define MAX_NODES 100000
#define F 16
#define NB 4
#define TROWH 256                 // halves per node

__device__ __align__(512) __half g_table[(size_t)MAX_NODES * TROWH];

#define PACK_F32X2(out, lo, hi) \
    asm("mov.b64 %0, {%1, %2};" : "=l"(out) : "f"(lo), "f"(hi))
#define UNPACK_F32X2(lo, hi, in) \
    asm("mov.b64 {%0, %1}, %2;" : "=f"(lo), "=f"(hi) : "l"(in))
#define FMA_F32X2(d, a, b, c) \
    asm("fma.rn.f32x2 %0, %1, %2, %3;" : "=l"(d) : "l"(a), "l"(b), "l"(c))
// memory halves order [lo, hi]
#define CVT_F16X2(u, lo, hi) \
    asm("cvt.rn.f16x2.f32 %0, %1, %2;" : "=r"(u) : "f"(hi), "f"(lo))

// ---------------------------------------------------------------------------
// Kernel 1: build. One warp per 8-node batch, both k-halves.
// ---------------------------------------------------------------------------
__global__ void build_table_kernel(
    const float* __restrict__ x,
    const float* __restrict__ w,
    int n_nodes)
{
    int lane  = threadIdx.x & 31;
    int warpG = blockIdx.x * 4 + (threadIdx.x >> 5);
    int k0    = lane >> 2;             // cell 0..7
    int k1    = k0 + 8;                // cell 8..15
    int q     = lane & 3;              // fout quad

    const float4* wf4 = reinterpret_cast<const float4*>(w);
    unsigned long long wlo0[F], whi0[F], wlo1[F], whi1[F];
#pragma unroll
    for (int fin = 0; fin < F; fin++) {
        float4 w0 = wf4[k0 * 64 + fin * 4 + q];
        float4 w1 = wf4[k1 * 64 + fin * 4 + q];
        PACK_F32X2(wlo0[fin], w0.x, w0.y);
        PACK_F32X2(whi0[fin], w0.z, w0.w);
        PACK_F32X2(wlo1[fin], w1.x, w1.y);
        PACK_F32X2(whi1[fin], w1.z, w1.w);
    }

    const float4* xf4 = reinterpret_cast<const float4*>(x);
    uint2* tb = reinterpret_cast<uint2*>(g_table);

    int n_warps  = gridDim.x * 4;
    int n_groups = (n_nodes + 7) >> 3;

    int my_node_off = lane >> 2;     // 0..7 node within batch
    int my_part     = lane & 3;      // float4 within node

    float4 xb_next = make_float4(0.f, 0.f, 0.f, 0.f);
    {
        int n = warpG * 8 + my_node_off;
        if (warpG < n_groups && n < n_nodes)
            xb_next = xf4[(size_t)n * 4 + my_part];
    }

    for (int grp = warpG; grp < n_groups; grp += n_warps) {
        float4 xb = xb_next;
        {
            int ng = grp + n_warps;
            int n  = ng * 8 + my_node_off;
            if (ng < n_groups && n < n_nodes)
                xb_next = xf4[(size_t)n * 4 + my_part];
        }

#pragma unroll
        for (int nl = 0; nl < 8; nl++) {
            int node = grp * 8 + nl;
            unsigned long long a00 = 0, a01 = 0, a10 = 0, a11 = 0;
#pragma unroll
            for (int j = 0; j < 4; j++) {
                int src = nl * 4 + j;
                float v0 = __shfl_sync(0xffffffffu, xb.x, src);
                float v1 = __shfl_sync(0xffffffffu, xb.y, src);
                float v2 = __shfl_sync(0xffffffffu, xb.z, src);
                float v3 = __shfl_sync(0xffffffffu, xb.w, src);
                unsigned long long xx;
                PACK_F32X2(xx, v0, v0);
                FMA_F32X2(a00, xx, wlo0[j * 4 + 0], a00);
                FMA_F32X2(a01, xx, whi0[j * 4 + 0], a01);
                FMA_F32X2(a10, xx, wlo1[j * 4 + 0], a10);
                FMA_F32X2(a11, xx, whi1[j * 4 + 0], a11);
                PACK_F32X2(xx, v1, v1);
                FMA_F32X2(a00, xx, wlo0[j * 4 + 1], a00);
                FMA_F32X2(a01, xx, whi0[j * 4 + 1], a01);
                FMA_F32X2(a10, xx, wlo1[j * 4 + 1], a10);
                FMA_F32X2(a11, xx, whi1[j * 4 + 1], a11);
                PACK_F32X2(xx, v2, v2);
                FMA_F32X2(a00, xx, wlo0[j * 4 + 2], a00);
                FMA_F32X2(a01, xx, whi0[j * 4 + 2], a01);
                FMA_F32X2(a10, xx, wlo1[j * 4 + 2], a10);
                FMA_F32X2(a11, xx, whi1[j * 4 + 2], a11);
                PACK_F32X2(xx, v3, v3);
                FMA_F32X2(a00, xx, wlo0[j * 4 + 3], a00);
                FMA_F32X2(a01, xx, whi0[j * 4 + 3], a01);
                FMA_F32X2(a10, xx, wlo1[j * 4 + 3], a10);
                FMA_F32X2(a11, xx, whi1[j * 4 + 3], a11);
            }
            if (node < n_nodes) {
                float f0, f1, f2, f3;
                uint2 val;
                size_t base = (size_t)node * 64;
                UNPACK_F32X2(f0, f1, a00);
                UNPACK_F32X2(f2, f3, a01);
                CVT_F16X2(val.x, f0, f1);
                CVT_F16X2(val.y, f2, f3);
                tb[base + k0 * 4 + q] = val;          // 256B/warp
                UNPACK_F32X2(f0, f1, a10);
                UNPACK_F32X2(f2, f3, a11);
                CVT_F16X2(val.x, f0, f1);
                CVT_F16X2(val.y, f2, f3);
                tb[base + k1 * 4 + q] = val;          // 256B/warp
            }
        }
    }
}

// ---------------------------------------------------------------------------
// Kernel 2: 8 lanes/edge, sector-exact.
//   lane sl: h = sl&1 (fout half), us = (sl>>1)&1, vs = sl>>2 (u/v offsets)
// ---------------------------------------------------------------------------
#define UNR 4
#define EPB 128   // 256 threads / 8 lanes * UNR
__global__ __launch_bounds__(256) void edge_kernel(
    const int* __restrict__ ei,
    const float* __restrict__ attr,
    float* __restrict__ out,
    int n_edges)
{
    int tid = threadIdx.x;
    int sl  = tid & 7;
    int g   = tid >> 3;              // edge slot 0..31
    int h   = sl & 1;
    int us  = (sl >> 1) & 1;
    int vs  = sl >> 2;

    const uint4* tb = reinterpret_cast<const uint4*>(g_table);

    bool  val[UNR];
    int   row[UNR];
    uint4 t[UNR];
    float wl[UNR];

#pragma unroll
    for (int i = 0; i < UNR; i++) {
        int e = blockIdx.x * EPB + g + 32 * i;
        val[i] = (e < n_edges);
        int ec = val[i] ? e : (n_edges - 1);

        row[i]   = ei[ec];
        int col  = ei[n_edges + ec];
        float2 a = reinterpret_cast<const float2*>(attr)[ec];

        float sx = fmaf(a.x, 1.5f, 1.5f);
        float sy = fmaf(a.y, 1.5f, 1.5f);
        float ixf = fminf(fmaxf(floorf(sx), 0.f), 2.f);
        float iyf = fminf(fmaxf(floorf(sy), 0.f), 2.f);
        float fx = sx - ixf;
        float fy = sy - iyf;
        int iu = (int)ixf;
        int iv = (int)iyf;

        float w11 = fx * fy;
        float w10 = fx - w11;
        float w01 = fy - w11;
        float w00 = 1.f - fx - fy + w11;

        // weight for (u = iu+us, v = iv+vs)
        wl[i] = us ? (vs ? w11 : w10) : (vs ? w01 : w00);

        // uint4 index: node*32 + u*8 + v*2 + h  (sector-exact 16B)
        size_t bi = (size_t)col * 32 + (iu + us) * 8 + (iv + vs) * 2 + h;
        t[i] = tb[bi];
    }

#pragma unroll
    for (int i = 0; i < UNR; i++) {
        const __half2* hp = reinterpret_cast<const __half2*>(&t[i]);
        float p[8];
#pragma unroll
        for (int j = 0; j < 4; j++) {
            float2 f = __half22float2(hp[j]);
            p[2 * j]     = wl[i] * f.x;
            p[2 * j + 1] = wl[i] * f.y;
        }
        // round 1: sum over vs (xor 4)
#pragma unroll
        for (int j = 0; j < 8; j++)
            p[j] += __shfl_xor_sync(0xffffffffu, p[j], 4);
        // round 2: split-exchange over us (xor 2)
        float fin0, fin1, fin2, fin3;
        {
            float s0 = us ? p[0] : p[4];
            float s1 = us ? p[1] : p[5];
            float s2 = us ? p[2] : p[6];
            float s3 = us ? p[3] : p[7];
            float r0 = __shfl_xor_sync(0xffffffffu, s0, 2);
            float r1 = __shfl_xor_sync(0xffffffffu, s1, 2);
            float r2 = __shfl_xor_sync(0xffffffffu, s2, 2);
            float r3 = __shfl_xor_sync(0xffffffffu, s3, 2);
            fin0 = (us ? p[4] : p[0]) + r0;
            fin1 = (us ? p[5] : p[1]) + r1;
            fin2 = (us ? p[6] : p[2]) + r2;
            fin3 = (us ? p[7] : p[3]) + r3;
        }
        // lanes vs==0 write quad (h*2 + us)
        if (val[i] && vs == 0) {
            float* op = out + (size_t)row[i] * F + (h * 2 + us) * 4;
            asm volatile("red.global.add.v4.f32 [%0], {%1, %2, %3, %4};"
                         :: "l"(op), "f"(fin0), "f"(fin1), "f"(fin2), "f"(fin3)
                         : "memory");
        }
    }
}

// ---------------------------------------------------------------------------
extern "C" void kernel_launch(void* const* d_in, const int* in_sizes, int n_in,
                              void* d_out, int out_size)
{
    const float* x    = (const float*)d_in[0];
    const int*   ei   = (const int*)d_in[1];
    const float* attr = (const float*)d_in[2];
    const float* w    = (const float*)d_in[3];
    float*       out  = (float*)d_out;

    int n_nodes = in_sizes[0] / F;       // 100000
    int n_edges = in_sizes[1] / 2;       // 1600000

    cudaMemsetAsync(d_out, 0, (size_t)out_size * sizeof(float));

    build_table_kernel<<<1184, 128>>>(x, w, n_nodes);

    int ek_blocks = (n_edges + EPB - 1) / EPB;
    edge_kernel<<<ek_blocks, 256>>>(ei, attr, out, n_edges);
}

// round 10
// speedup vs baseline: 1.2628x; 1.2628x over previous
#include <cuda_runtime.h>
#include <cuda_fp16.h>
#include <cstdint>

// ---------------------------------------------------------------------------
// BasisConvLayer (mode='conv', linear hat basis 4x4, F_in=F_out=16)
//
// FP16 table  T[node][u:4][v:4][fout:16]  (512 B/node, 51 MB).
//   Kernel 1 (build): one warp per 8-node batch covers BOTH k-halves
//     (W in f32x2 regs). x staged in smem as DUPLICATED f32x2 pairs once per
//     group (4 pack + 4 STS.64 per lane); compute loop: 16 uniform LDS.64 +
//     64 FFMA2 per node — no shfl, no per-node pack.
//   Kernel 2 (edge): R6-proven config: 4 lanes/edge x 2 edges/thread;
//     2 LDG.128/lane; split shfl_xor(2) combine; red.global.add.v4.
// ---------------------------------------------------------------------------

#define MAX_NODES 100000
#define F 16
#define NB 4
#define TROWH 256                 // halves per node

__device__ __align__(512) __half g_table[(size_t)MAX_NODES * TROWH];

#define PACK_F32X2(out, lo, hi) \
    asm("mov.b64 %0, {%1, %2};" : "=l"(out) : "f"(lo), "f"(hi))
#define UNPACK_F32X2(lo, hi, in) \
    asm("mov.b64 {%0, %1}, %2;" : "=f"(lo), "=f"(hi) : "l"(in))
#define FMA_F32X2(d, a, b, c) \
    asm("fma.rn.f32x2 %0, %1, %2, %3;" : "=l"(d) : "l"(a), "l"(b), "l"(c))
// memory halves order [lo, hi]
#define CVT_F16X2(u, lo, hi) \
    asm("cvt.rn.f16x2.f32 %0, %1, %2;" : "=r"(u) : "f"(hi), "f"(lo))

#define XPS 17                    // padded u64 stride per node (bank-friendly)

// ---------------------------------------------------------------------------
// Kernel 1: build. One warp per 8-node batch, both k-halves, smem x-pairs.
// ---------------------------------------------------------------------------
__global__ void build_table_kernel(
    const float* __restrict__ x,
    const float* __restrict__ w,
    int n_nodes)
{
    __shared__ unsigned long long xp[4][8 * XPS];   // per-warp staging

    int lane  = threadIdx.x & 31;
    int warpL = threadIdx.x >> 5;
    int warpG = blockIdx.x * 4 + warpL;
    int k0    = lane >> 2;             // cell 0..7
    int k1    = k0 + 8;                // cell 8..15
    int q     = lane & 3;              // fout quad

    const float4* wf4 = reinterpret_cast<const float4*>(w);
    unsigned long long wlo0[F], whi0[F], wlo1[F], whi1[F];
#pragma unroll
    for (int fin = 0; fin < F; fin++) {
        float4 w0 = wf4[k0 * 64 + fin * 4 + q];
        float4 w1 = wf4[k1 * 64 + fin * 4 + q];
        PACK_F32X2(wlo0[fin], w0.x, w0.y);
        PACK_F32X2(whi0[fin], w0.z, w0.w);
        PACK_F32X2(wlo1[fin], w1.x, w1.y);
        PACK_F32X2(whi1[fin], w1.z, w1.w);
    }

    const float4* xf4 = reinterpret_cast<const float4*>(x);
    uint2* tb = reinterpret_cast<uint2*>(g_table);

    int n_warps  = gridDim.x * 4;
    int n_groups = (n_nodes + 7) >> 3;

    int my_node_off = lane >> 2;     // 0..7 node within batch
    int my_part     = lane & 3;      // float4 within node (fin 4m..4m+3)

    float4 xb_next = make_float4(0.f, 0.f, 0.f, 0.f);
    {
        int n = warpG * 8 + my_node_off;
        if (warpG < n_groups && n < n_nodes)
            xb_next = xf4[(size_t)n * 4 + my_part];
    }

    for (int grp = warpG; grp < n_groups; grp += n_warps) {
        float4 xb = xb_next;
        {
            int ng = grp + n_warps;
            int n  = ng * 8 + my_node_off;
            if (ng < n_groups && n < n_nodes)
                xb_next = xf4[(size_t)n * 4 + my_part];
        }

        // stage duplicated pairs: xp[warp][node*XPS + fin] = (v, v)
        {
            unsigned long long p0, p1, p2, p3;
            PACK_F32X2(p0, xb.x, xb.x);
            PACK_F32X2(p1, xb.y, xb.y);
            PACK_F32X2(p2, xb.z, xb.z);
            PACK_F32X2(p3, xb.w, xb.w);
            int base = my_node_off * XPS + my_part * 4;
            xp[warpL][base + 0] = p0;
            xp[warpL][base + 1] = p1;
            xp[warpL][base + 2] = p2;
            xp[warpL][base + 3] = p3;
        }
        __syncwarp();

#pragma unroll
        for (int nl = 0; nl < 8; nl++) {
            int node = grp * 8 + nl;
            const unsigned long long* xrow = &xp[warpL][nl * XPS];
            unsigned long long a00 = 0, a01 = 0, a10 = 0, a11 = 0;
#pragma unroll
            for (int fin = 0; fin < F; fin++) {
                unsigned long long xx = xrow[fin];   // uniform LDS.64 bcast
                FMA_F32X2(a00, xx, wlo0[fin], a00);
                FMA_F32X2(a01, xx, whi0[fin], a01);
                FMA_F32X2(a10, xx, wlo1[fin], a10);
                FMA_F32X2(a11, xx, whi1[fin], a11);
            }
            if (node < n_nodes) {
                float f0, f1, f2, f3;
                uint2 val;
                size_t base = (size_t)node * 64;
                UNPACK_F32X2(f0, f1, a00);
                UNPACK_F32X2(f2, f3, a01);
                CVT_F16X2(val.x, f0, f1);
                CVT_F16X2(val.y, f2, f3);
                tb[base + k0 * 4 + q] = val;          // 256B/warp
                UNPACK_F32X2(f0, f1, a10);
                UNPACK_F32X2(f2, f3, a11);
                CVT_F16X2(val.x, f0, f1);
                CVT_F16X2(val.y, f2, f3);
                tb[base + k1 * 4 + q] = val;          // 256B/warp
            }
        }
        __syncwarp();
    }
}

// ---------------------------------------------------------------------------
// Kernel 2: edge (R6-proven). 4 lanes/edge, 2 edges/thread.
// ---------------------------------------------------------------------------
#define EPB 128
__global__ __launch_bounds__(256) void edge_kernel(
    const int* __restrict__ ei,
    const float* __restrict__ attr,
    float* __restrict__ out,
    int n_edges)
{
    int tid = threadIdx.x;
    int sl  = tid & 3;
    int g   = tid >> 2;

    const uint4* tb = reinterpret_cast<const uint4*>(g_table);

    int  e[2] = { blockIdx.x * EPB + g, blockIdx.x * EPB + g + 64 };
    bool val[2];
    int  row[2];
    uint4 u0[2], u1[2];
    float wa[2], wb[2];

#pragma unroll
    for (int i = 0; i < 2; i++) {
        val[i] = (e[i] < n_edges);
        int ec = val[i] ? e[i] : (n_edges - 1);

        row[i]   = ei[ec];
        int col  = ei[n_edges + ec];
        float2 a = reinterpret_cast<const float2*>(attr)[ec];

        float sx = fmaf(a.x, 1.5f, 1.5f);
        float sy = fmaf(a.y, 1.5f, 1.5f);
        float ixf = fminf(fmaxf(floorf(sx), 0.f), 2.f);
        float iyf = fminf(fmaxf(floorf(sy), 0.f), 2.f);
        float fx = sx - ixf;
        float fy = sy - iyf;
        int iu = (int)ixf;
        int iv = (int)iyf;

        float w11 = fx * fy;
        float w10 = fx - w11;
        float w01 = fy - w11;
        float w00 = 1.f - fx - fy + w11;

        wa[i] = (sl < 2) ? w00 : w01;   // u = iu   (v per lane pair)
        wb[i] = (sl < 2) ? w10 : w11;   // u = iu+1

        size_t bi = (size_t)col * 32 + (iu * 4 + iv) * 2 + sl;
        u0[i] = tb[bi];
        u1[i] = tb[bi + 8];
    }

#pragma unroll
    for (int i = 0; i < 2; i++) {
        const __half2* h0 = reinterpret_cast<const __half2*>(&u0[i]);
        const __half2* h1 = reinterpret_cast<const __half2*>(&u1[i]);
        float p[8];
#pragma unroll
        for (int j = 0; j < 4; j++) {
            float2 f0 = __half22float2(h0[j]);
            float2 f1 = __half22float2(h1[j]);
            p[2 * j]     = fmaf(wa[i], f0.x, wb[i] * f1.x);
            p[2 * j + 1] = fmaf(wa[i], f0.y, wb[i] * f1.y);
        }
        bool hi = (sl & 2);
        float fin0, fin1, fin2, fin3;
        {
            float s0 = hi ? p[0] : p[4];
            float s1 = hi ? p[1] : p[5];
            float s2 = hi ? p[2] : p[6];
            float s3 = hi ? p[3] : p[7];
            float r0 = __shfl_xor_sync(0xffffffffu, s0, 2);
            float r1 = __shfl_xor_sync(0xffffffffu, s1, 2);
            float r2 = __shfl_xor_sync(0xffffffffu, s2, 2);
            float r3 = __shfl_xor_sync(0xffffffffu, s3, 2);
            fin0 = (hi ? p[4] : p[0]) + r0;
            fin1 = (hi ? p[5] : p[1]) + r1;
            fin2 = (hi ? p[6] : p[2]) + r2;
            fin3 = (hi ? p[7] : p[3]) + r3;
        }
        if (val[i]) {
            int quad = (sl & 1) * 2 + (sl >> 1);
            float* op = out + (size_t)row[i] * F + quad * 4;
            asm volatile("red.global.add.v4.f32 [%0], {%1, %2, %3, %4};"
                         :: "l"(op), "f"(fin0), "f"(fin1), "f"(fin2), "f"(fin3)
                         : "memory");
        }
    }
}

// ---------------------------------------------------------------------------
extern "C" void kernel_launch(void* const* d_in, const int* in_sizes, int n_in,
                              void* d_out, int out_size)
{
    const float* x    = (const float*)d_in[0];
    const int*   ei   = (const int*)d_in[1];
    const float* attr = (const float*)d_in[2];
    const float* w    = (const float*)d_in[3];
    float*       out  = (float*)d_out;

    int n_nodes = in_sizes[0] / F;       // 100000
    int n_edges = in_sizes[1] / 2;       // 1600000

    cudaMemsetAsync(d_out, 0, (size_t)out_size * sizeof(float));

    build_table_kernel<<<1184, 128>>>(x, w, n_nodes);

    int ek_blocks = (n_edges + EPB - 1) / EPB;
    edge_kernel<<<ek_blocks, 256>>>(ei, attr, out, n_edges);
}